// round 16
// baseline (speedup 1.0000x reference)
#include <cuda_runtime.h>
#include <cuda_bf16.h>
#include <cstdint>

// ---------------------------------------------------------------------------
// TimemixingFC_channel, round 16: FP8 (e4m3, m16n8k32) — halve the HMMA count.
//   Six structural rounds left per-phase time invariant at ~14.5us ->
//   mma.sync throughput ceiling (~30cyc/HMMA/SMSP). m16n8k32.e4m3 does 2x K
//   per instruction at the same issue cost; the b16-ldmatrix fragment trick
//   maps byte-exactly onto the e4m3 fragments, so the proven skeleton keeps
//   working with 3 k-steps instead of 6.
//   Numerics: fp32 accumulate; power-of-2 per-tensor scales (x:1, W:512,
//   W':4096, o0:32, o1:4096) folded into the bias FMA; G/o/bias fp32.
//   Structure = R15: single launch, grid 291 (256 work + 35 side), generation
//   counters, local neighbor sync.
// ---------------------------------------------------------------------------

#define SMEM_BYTES 51712

static __device__ __align__(16) uint8_t g_mid[32768 * 96];     // o0 (e4m3, x32)
static __device__ __align__(16) uint8_t g_wbf[2][288 * 112];   // qkv W images
static __device__ __align__(16) uint8_t g_wpbf[96 * 112];      // projs_w image
static __device__ float g_b1[288];                             // b' fold bias
static __device__ int   g_flag[256];
static __device__ int   g_tr;
static __device__ int   g_fold;

// scales
#define SW_Q   512.0f      // lr_w / projs_w images
#define SW_F   4096.0f     // W' image
#define SO0    32.0f       // o0 store scale
#define SO1    4096.0f     // o1 store scale
#define INVQ0  (1.0f / 512.0f)          // branch0 qkv descale (1 * 512)
#define INVQ1  (1.0f / 131072.0f)       // branch1 qkv descale (32 * 4096)
#define INVP   (1.0f / 2097152.0f)      // proj descale (4096 * 512)

// ---- PTX helpers (valid under compute_100) --------------------------------
__device__ __forceinline__ uint32_t smem_u32(const void* p) {
    uint32_t a;
    asm("{ .reg .u64 t; cvta.to.shared.u64 t, %1; cvt.u32.u64 %0, t; }" : "=r"(a) : "l"(p));
    return a;
}
#define CPA16(dst, src) \
    asm volatile("cp.async.cg.shared.global [%0], [%1], 16;" :: "r"(dst), "l"(src) : "memory")
#define CPA_COMMIT() asm volatile("cp.async.commit_group;" ::: "memory")
#define CPA_WAIT(n)  asm volatile("cp.async.wait_group %0;" :: "n"(n) : "memory")

__device__ __forceinline__ void ldsm4(uint32_t& r0, uint32_t& r1, uint32_t& r2,
                                      uint32_t& r3, uint32_t addr) {
    asm volatile("ldmatrix.sync.aligned.m8n8.x4.shared.b16 {%0,%1,%2,%3}, [%4];"
                 : "=r"(r0), "=r"(r1), "=r"(r2), "=r"(r3) : "r"(addr));
}
#define MMA8(acc, a, b0, b1) \
    asm volatile("mma.sync.aligned.m16n8k32.row.col.f32.e4m3.e4m3.f32 " \
        "{%0,%1,%2,%3}, {%4,%5,%6,%7}, {%8,%9}, {%0,%1,%2,%3};" \
        : "+f"((acc)[0]), "+f"((acc)[1]), "+f"((acc)[2]), "+f"((acc)[3]) \
        : "r"((a)[0]), "r"((a)[1]), "r"((a)[2]), "r"((a)[3]), "r"(b0), "r"(b1))

// pack two floats -> two e4m3 bytes: low byte = lo, high byte = hi
__device__ __forceinline__ uint16_t e4m3x2(float hi, float lo) {
    uint16_t r;
    asm("cvt.rn.satfinite.e4m3x2.f32 %0, %1, %2;" : "=h"(r) : "f"(hi), "f"(lo));
    return r;
}
__device__ __forceinline__ uint8_t e4m3(float f) {
    return (uint8_t)e4m3x2(0.f, f);
}

// ---------------------------------------------------------------------------
// One n-tile pair (tiles 2p, 2p+1): D[16x16] over K=96 (3 ksteps of 32).
// ---------------------------------------------------------------------------
__device__ __forceinline__ void hmma_pair(const uint32_t af[3][4], uint32_t wAddr,
                                          int p, float acc[2][4])
{
#pragma unroll
    for (int t = 0; t < 2; t++)
#pragma unroll
        for (int r = 0; r < 4; r++) acc[t][r] = 0.f;
#pragma unroll
    for (int ks = 0; ks < 3; ks++) {
        uint32_t b0, b1, b2, b3;
        ldsm4(b0, b1, b2, b3, wAddr + p * 1792 + ks * 32);
        MMA8(acc[0], af[ks], b0, b2);
        MMA8(acc[1], af[ks], b1, b3);
    }
}

// stage one 96x112-e4m3 weight image (10752B = 672 x 16B) via cp.async
__device__ __forceinline__ void stage_w_async(uint32_t dst, const uint8_t* src, int tid)
{
    for (int f = tid; f < 672; f += 256)
        CPA16(dst + f * 16, src + f * 16);
}

// ---------------------------------------------------------------------------
// Side blocks (bid >= 256):
//   256..273: W' fold (16 rows each, fp32 math, e4m3*4096 store) -> g_fold++
//   274:      b' (fp32)                                          -> g_fold++
//   275..278: projs_w -> e4m3*512 image                          -> g_fold++
//   279..290: lr_w    -> e4m3*512 image                          -> g_tr++
// ---------------------------------------------------------------------------
__device__ void side_block(char* smem, int bid, int tid,
                           const float* lr, const float* pr,
                           const float* sw, const float* swb,
                           const float* prb, const float* prs_ext)
{
    float* prs  = (float*)smem;             // [96][100] fp32
    float* sws  = (float*)(smem + 38400);   // [16][96] fp32
    float* prbs = (float*)(smem + 44544);   // [96]
    int* ctr = &g_fold;

    if (bid < 274) {
        int jf0 = (bid - 256) * 16;
        for (int i = tid; i < 2304; i += 256) {
            int t = i / 24, c4 = (i % 24) * 4;
            *(float4*)&prs[t * 100 + c4] = *(const float4*)&pr[t * 96 + c4];
        }
        for (int i = tid; i < 1536; i += 256)
            sws[i] = sw[jf0 * 96 + i];
        __syncthreads();

        int rgrp = tid >> 4, cgrp = tid & 15;
        int c0 = cgrp * 6;
        const float* swr = &sws[rgrp * 96];
        float acc[6];
#pragma unroll
        for (int j = 0; j < 6; j++) acc[j] = 0.f;
#pragma unroll 4
        for (int t = 0; t < 96; t++) {
            float s = swr[t];
#pragma unroll
            for (int j = 0; j < 6; j++)
                acc[j] = fmaf(s, prs[t * 100 + c0 + j], acc[j]);
        }
        int jf = jf0 + rgrp;
#pragma unroll
        for (int j = 0; j < 6; j++)
            g_wbf[1][jf * 112 + c0 + j] = e4m3(acc[j] * SW_F);
    } else if (bid == 274) {
        if (tid < 96) prbs[tid] = prb[tid];
        __syncthreads();
        int rgrp = tid >> 4, cgrp = tid & 15;
        int c0 = cgrp * 6;
        for (int r = rgrp; r < 288; r += 16) {
            const float* swr = sw + r * 96;
            float pacc = 0.f;
#pragma unroll
            for (int t = 0; t < 6; t++)
                pacc = fmaf(swr[c0 + t], prbs[c0 + t], pacc);
#pragma unroll
            for (int off = 1; off < 16; off <<= 1)
                pacc += __shfl_xor_sync(0xffffffffu, pacc, off);
            if (cgrp == 0) g_b1[r] = pacc + swb[r];
        }
    } else if (bid < 279) {
        int base = (bid - 275) * 2304;
#pragma unroll
        for (int k = 0; k < 9; k++) {
            int idx = base + k * 256 + tid;   // < 9216
            int j = idx / 96, c = idx % 96;
            g_wpbf[j * 112 + c] = e4m3(prs_ext[idx] * SW_Q);
        }
    } else {
        int base = (bid - 279) * 2304;
#pragma unroll
        for (int k = 0; k < 9; k++) {
            int idx = base + k * 256 + tid;   // < 27648
            int jf = idx / 96, c = idx % 96;
            g_wbf[0][jf * 112 + c] = e4m3(lr[idx] * SW_Q);
        }
        ctr = &g_tr;
    }
    __threadfence();
    __syncthreads();
    if (tid == 0) atomicAdd(ctr, 1);
}

// ---------------------------------------------------------------------------
// One branch phase. BR=0: x -> o0 (g_mid). BR=1: o0 -> out.
// ---------------------------------------------------------------------------
template <int BR>
__device__ __forceinline__ void run_phase(char* smem, uint32_t sb,
                                          const float* __restrict__ xin_ext,
                                          const float* __restrict__ QB,
                                          const float* __restrict__ pr_b,
                                          float* __restrict__ out_ext,
                                          int shift, int bid, int f0)
{
    int*   tb = (int*)smem;
    float* qb = (float*)(smem + 512);
    float* pb = (float*)(smem + 1664);
    float* gt = (float*)(smem + 2048);
    float* gc = (float*)(smem + 4096);
    char*  smA = smem + 5120;               // [128][112] e4m3 (x / o tile)
    uint32_t smAu = sb + 5120;
    uint32_t smWu = sb + 19456;             // 3 x [96][112] e4m3 slots

    const float INVQ = BR ? INVQ1 : INVQ0;
    const float SO   = BR ? SO1 : SO0;

    int tid = threadIdx.x, w = tid >> 5, lane = tid & 31;
    int g = lane >> 2, tig = lane & 3;
    int l16 = lane & 15, lh = lane >> 4;
    int row0 = w * 16;

    if (BR && tid < 96) pb[tid] = pr_b[tid];

    if (tid < 128) {
        int pi = tid & 63;
        int gg = (bid << 6) + pi;
        int b = gg >> 13, dw = (gg >> 10) & 7, p = gg & 1023;
        int d = (2 * dw + (tid >> 6) + shift) & 15;
        tb[tid] = ((b * 16 + d) * 1024 + p) * 96;
    }

    const uint8_t* WB = g_wbf[BR];

    if (BR == 0) {
        __syncthreads();   // tb ready
        // A tile from x (fp32 -> e4m3); overlaps lr-transpose side blocks
        for (int f4 = tid; f4 < 3072; f4 += 256) {
            int l = f4 / 24, q4 = f4 % 24;
            float4 v = *(const float4*)&xin_ext[tb[l] + q4 * 4];
            uint32_t pk = (uint32_t)e4m3x2(v.y, v.x)
                        | ((uint32_t)e4m3x2(v.w, v.z) << 16);
            *(uint32_t*)(smA + l * 112 + q4 * 4) = pk;
        }
        for (int i = tid; i < 288; i += 256) qb[i] = QB[i];
        if (tid == 0)
            while (*(volatile int*)&g_tr < 12 * (f0 + 1)) {}
        __syncthreads();
        __threadfence();
        stage_w_async(smWu,             WB + 96 * 112, tid);   // K
        stage_w_async(smWu + 10752,     WB + 192 * 112, tid);  // V
        stage_w_async(smWu + 2 * 10752, WB,             tid);  // Q
        CPA_COMMIT();
    } else {
        for (int i = tid; i < 288; i += 256) qb[i] = QB[i];
        __syncthreads();   // tb ready
        for (int f = tid; f < 768; f += 256) {        // A tile (o0 e4m3) via L2
            int l = f / 6, u = f % 6;
            CPA16(smAu + l * 112 + u * 16, g_mid + (size_t)tb[l] + u * 16);
        }
        stage_w_async(smWu,             WB + 96 * 112, tid);   // K'
        stage_w_async(smWu + 10752,     WB + 192 * 112, tid);  // V'
        stage_w_async(smWu + 2 * 10752, WB,             tid);  // Q'
        CPA_COMMIT();
    }

    uint32_t aAddr = smAu + (row0 + l16) * 112 + lh * 16;
    uint32_t wAddr = smWu + l16 * 112 + lh * 16;

    CPA_WAIT(0);
    __syncthreads();        // A + K + V + Q visible

    uint32_t af[3][4];
#pragma unroll
    for (int ks = 0; ks < 3; ks++)
        ldsm4(af[ks][0], af[ks][1], af[ks][2], af[ks][3], aAddr + ks * 32);

    // ---- mega loop: K, V, Q per pair; K/V fold into G; Q held in regs ----
    float G[8];
    float qacc[6][2][4];
#pragma unroll
    for (int i = 0; i < 8; i++) G[i] = 0.f;
#pragma unroll
    for (int p = 0; p < 6; p++) {
        float ka[2][4], va[2][4];
        hmma_pair(af, wAddr,             p, ka);
        hmma_pair(af, wAddr + 10752,     p, va);
        hmma_pair(af, wAddr + 2 * 10752, p, qacc[p]);
#pragma unroll
        for (int t = 0; t < 2; t++) {
            int j0 = (2 * p + t) * 8 + tig * 2;
            float kb0 = qb[96 + j0], kb1 = qb[96 + j0 + 1];
            float vb0 = qb[192 + j0], vb1 = qb[192 + j0 + 1];
            float k0 = fmaf(ka[t][0], INVQ, kb0), k1 = fmaf(ka[t][1], INVQ, kb1);
            float k2 = fmaf(ka[t][2], INVQ, kb0), k3 = fmaf(ka[t][3], INVQ, kb1);
            float v0 = fmaf(va[t][0], INVQ, vb0), v1 = fmaf(va[t][1], INVQ, vb1);
            float v2 = fmaf(va[t][2], INVQ, vb0), v3 = fmaf(va[t][3], INVQ, vb1);
            G[0] = fmaf(k0, v0, G[0]); G[1] = fmaf(k0, v1, G[1]);
            G[2] = fmaf(k1, v0, G[2]); G[3] = fmaf(k1, v1, G[3]);
            G[4] = fmaf(k2, v2, G[4]); G[5] = fmaf(k2, v3, G[5]);
            G[6] = fmaf(k3, v2, G[6]); G[7] = fmaf(k3, v3, G[7]);
        }
    }
    __syncthreads();        // all warps done reading weight slots

    if (BR) { stage_w_async(smWu, g_wpbf, tid); CPA_COMMIT(); }

#pragma unroll
    for (int off = 1; off <= 2; off <<= 1)
#pragma unroll
        for (int i = 0; i < 8; i++)
            G[i] += __shfl_xor_sync(0xffffffffu, G[i], off);
    if (tig == 0) {
        *(float4*)&gt[(row0 + g) * 4]     = make_float4(G[0], G[1], G[2], G[3]);
        *(float4*)&gt[(row0 + g + 8) * 4] = make_float4(G[4], G[5], G[6], G[7]);
    }
    __syncthreads();
    if (tid < 64) {
        float4 a = *(float4*)&gt[tid * 4];
        float4 b4 = *(float4*)&gt[(tid + 64) * 4];
        *(float4*)&gc[tid * 4] =
            make_float4(a.x + b4.x, a.y + b4.y, a.z + b4.z, a.w + b4.w);
    }
    CPA_WAIT(0);
    __syncthreads();        // gc (+ proj weights) visible

    float4 Glo = *(float4*)&gc[((row0 + g) & 63) * 4];
    float4 Ghi = *(float4*)&gc[((row0 + g + 8) & 63) * 4];

    // ---- o = (qacc*INVQ + b) @ G -> e4m3 (x SO) into own smA rows ----
#pragma unroll
    for (int p = 0; p < 6; p++) {
#pragma unroll
        for (int t = 0; t < 2; t++) {
            int j0 = (2 * p + t) * 8 + tig * 2;
            float b0 = qb[j0], b1 = qb[j0 + 1];
            float q0 = fmaf(qacc[p][t][0], INVQ, b0), q1 = fmaf(qacc[p][t][1], INVQ, b1);
            float q2 = fmaf(qacc[p][t][2], INVQ, b0), q3 = fmaf(qacc[p][t][3], INVQ, b1);
            float o0 = q0 * Glo.x + q1 * Glo.z;
            float o1 = q0 * Glo.y + q1 * Glo.w;
            float o2 = q2 * Ghi.x + q3 * Ghi.z;
            float o3 = q2 * Ghi.y + q3 * Ghi.w;
            *(uint16_t*)(smA + (row0 + g) * 112 + j0)     = e4m3x2(o1 * SO, o0 * SO);
            *(uint16_t*)(smA + (row0 + g + 8) * 112 + j0) = e4m3x2(o3 * SO, o2 * SO);
        }
    }

    if (BR == 0) {
        __syncthreads();
        for (int f = tid; f < 768; f += 256) {
            int l = f / 6, u = f % 6;
            *(uint4*)(g_mid + (size_t)tb[l] + u * 16) =
                *(const uint4*)(smA + l * 112 + u * 16);
        }
    } else {
        __syncwarp();       // order own-warp STS -> LDSM
        uint32_t of[3][4];
#pragma unroll
        for (int ks = 0; ks < 3; ks++)
            ldsm4(of[ks][0], of[ks][1], of[ks][2], of[ks][3], aAddr + ks * 32);
        int tbg = tb[row0 + g], tbh = tb[row0 + g + 8];
#pragma unroll
        for (int p = 0; p < 6; p++) {
            float pa[2][4];
            hmma_pair(of, wAddr, p, pa);     // slot0 = proj weights
#pragma unroll
            for (int t = 0; t < 2; t++) {
                int j0 = (2 * p + t) * 8 + tig * 2;
                float b0 = pb[j0], b1 = pb[j0 + 1];
                *(float2*)&out_ext[tbg + j0] =
                    make_float2(fmaf(pa[t][0], INVP, b0), fmaf(pa[t][1], INVP, b1));
                *(float2*)&out_ext[tbh + j0] =
                    make_float2(fmaf(pa[t][2], INVP, b0), fmaf(pa[t][3], INVP, b1));
            }
        }
    }
}

// ---------------------------------------------------------------------------
// Mega kernel. Grid 291 x 256 (256 work + 35 side), all resident in wave 1.
// ---------------------------------------------------------------------------
__global__ void __launch_bounds__(256, 2)
fused_mega(const float* __restrict__ x,
           const float* __restrict__ lr_w,
           const float* __restrict__ lr_b,
           const float* __restrict__ projs_b,
           float* __restrict__ out,
           const float* __restrict__ f_pr,    // proj_w
           const float* __restrict__ f_sw,    // sw_w
           const float* __restrict__ f_swb,   // sw_b
           const float* __restrict__ f_prb,   // proj_b
           const float* __restrict__ f_prs)   // projs_w
{
    extern __shared__ char smem[];
    int tid = threadIdx.x, bid = blockIdx.x;

    if (bid >= 256) {
        side_block(smem, bid, tid, lr_w, f_pr, f_sw, f_swb, f_prb, f_prs);
        return;
    }

    uint32_t sb = smem_u32(smem);

    int f0 = 0;
    if (tid == 0) f0 = *(volatile int*)&g_flag[bid];

    // ---- phase A: branch 0, pairs (2w, 2w+1), x -> o0 ----
    run_phase<0>(smem, sb, x, lr_b, nullptr, nullptr, 0, bid, f0);

    __threadfence();
    __syncthreads();
    if (tid == 0) atomicExch(&g_flag[bid], f0 + 1);

    // ---- wait: dw-1 neighbor's phase A + all fold/transpose side blocks ----
    if (tid == 0) {
        int dw = (bid >> 4) & 7;
        int dep = (bid & 0x8F) | (((dw + 7) & 7) << 4);
        while (*(volatile int*)&g_fold < 23 * (f0 + 1)) {}
        while (*(volatile int*)&g_flag[dep] <= f0) {}
    }
    __syncthreads();
    __threadfence();

    // ---- phase B: branch 1, pairs (2w-1, 2w), o0 -> out ----
    run_phase<1>(smem, sb, nullptr, g_b1, projs_b, out, 15, bid, f0);
}

// ---------------------------------------------------------------------------
extern "C" void kernel_launch(void* const* d_in, const int* in_sizes, int n_in,
                              void* d_out, int out_size)
{
    const float* x       = (const float*)d_in[0];
    const float* lr_w    = (const float*)d_in[1];
    const float* lr_b    = (const float*)d_in[2];
    const float* proj_w  = (const float*)d_in[3];
    const float* proj_b  = (const float*)d_in[4];
    const float* sw_w    = (const float*)d_in[5];
    const float* sw_b    = (const float*)d_in[6];
    const float* projs_w = (const float*)d_in[7];
    const float* projs_b = (const float*)d_in[8];
    float* out = (float*)d_out;

    cudaFuncSetAttribute(fused_mega,
                         cudaFuncAttributeMaxDynamicSharedMemorySize, SMEM_BYTES);

    fused_mega<<<291, 256, SMEM_BYTES>>>(x, lr_w, lr_b, projs_b, out,
                                         proj_w, sw_w, sw_b, proj_b, projs_w);
}